// round 8
// baseline (speedup 1.0000x reference)
#include <cuda_runtime.h>
#include <math.h>

#define BB 2
#define LL 32
#define NSLOPE 0.01f

// ---------------- scratch (static __device__, no allocs) ----------------
__device__ float g_h1p0[2*4*128*128];
__device__ float g_h1p1[2*8*64*64];
__device__ float g_h1p2[2*16*32*32];
__device__ float g_h1p3[2*16*16*16];

__device__ float g_f0[2*4*256*256];
__device__ float g_f1[2*8*128*128];
__device__ float g_f2[2*16*64*64];
__device__ float g_f3[2*16*32*32];

__device__ float g_h2p0[2*4*128*128];
__device__ float g_h2p1[2*8*64*64];
__device__ float g_h2p2[2*16*32*32];
__device__ float g_h2p3[2*16*16*16];

__device__ float g_attn0[64*128*128];
__device__ float g_attn1[64*64*64];
__device__ float g_attn2[64*32*32];
__device__ float g_attn3[64*16*16];

__device__ float g_d0[64*16*32*32];
__device__ float g_d1[64*8*64*64];
__device__ float g_d2[64*4*128*128];

static inline int cdiv(int a, int b) { return (a + b - 1) / b; }

__device__ __forceinline__ float leaky(float v) { return v >= 0.f ? v : NSLOPE * v; }

// Build per-parity 2x2 effective kernel from a 3x3 kernel (upsample-nearest folding).
__device__ __forceinline__ void build_eff(const float* wk, int ey, int ex, float* e) {
    float rs[2][3];
    if (ey == 0) {
        rs[0][0] = wk[0]; rs[0][1] = wk[1]; rs[0][2] = wk[2];
        rs[1][0] = wk[3] + wk[6]; rs[1][1] = wk[4] + wk[7]; rs[1][2] = wk[5] + wk[8];
    } else {
        rs[0][0] = wk[0] + wk[3]; rs[0][1] = wk[1] + wk[4]; rs[0][2] = wk[2] + wk[5];
        rs[1][0] = wk[6]; rs[1][1] = wk[7]; rs[1][2] = wk[8];
    }
#pragma unroll
    for (int a = 0; a < 2; a++) {
        if (ex == 0) { e[a * 2 + 0] = rs[a][0]; e[a * 2 + 1] = rs[a][1] + rs[a][2]; }
        else         { e[a * 2 + 0] = rs[a][0] + rs[a][1]; e[a * 2 + 1] = rs[a][2]; }
    }
}

// ============ encoder: conv5x5+leaky[+feats]+maxpool2, ci-split S, both paths (z) ============
template<int CI, int CO, int COG, int H, int S, int PPB>
__global__ void enc_conv3_t(const float* __restrict__ in2, const float* __restrict__ in1,
                            const float* __restrict__ w, const float* __restrict__ bias,
                            float* __restrict__ f, float* __restrict__ pooled2,
                            float* __restrict__ pooled1) {
    constexpr int HP = H / 2;
    constexpr int NG = CO / COG;
    constexpr int CIG = CI / S;
    static_assert(CI % S == 0, "");
    static_assert((HP * HP) % PPB == 0, "");
    __shared__ float ws[COG * CI * 25];
    __shared__ float red[(S > 1) ? (S - 1) * PPB * COG * 4 : 1];

    int bly = blockIdx.y;
    int cog = bly % NG;
    int n = bly / NG;
    int co0 = cog * COG;
    bool path2 = (blockIdx.z == 0);
    const float* in = path2 ? in2 : in1;
    float* pooled = path2 ? pooled2 : pooled1;

    int tx = threadIdx.x, ty = threadIdx.y;
    int tid = ty * PPB + tx;
    for (int i = tid; i < COG * CI * 25; i += PPB * S)
        ws[i] = w[co0 * CI * 25 + i];
    __syncthreads();

    int p = blockIdx.x * PPB + tx;
    int px = p % HP, py = p / HP;

    float acc[COG][2][2] = {};

    const float* ib = in + (size_t)n * CI * H * H;
#pragma unroll
    for (int i = 0; i < CIG; i++) {
        int ci = ty * CIG + i;
        const float* src = ib + ci * H * H;
        float v[6][6];
#pragma unroll
        for (int r = 0; r < 6; r++) {
            int yy = 2 * py - 2 + r;
            bool oy = (unsigned)yy < (unsigned)H;
#pragma unroll
            for (int c = 0; c < 6; c++) {
                int xx = 2 * px - 2 + c;
                v[r][c] = (oy && (unsigned)xx < (unsigned)H) ? __ldg(src + yy * H + xx) : 0.f;
            }
        }
#pragma unroll
        for (int g = 0; g < COG; g++)
#pragma unroll
            for (int dy = 0; dy < 2; dy++)
#pragma unroll
                for (int dx = 0; dx < 2; dx++)
#pragma unroll
                    for (int ky = 0; ky < 5; ky++)
#pragma unroll
                        for (int kx = 0; kx < 5; kx++)
                            acc[g][dy][dx] += v[dy + ky][dx + kx] * ws[(g * CI + ci) * 25 + ky * 5 + kx];
    }

    if constexpr (S > 1) {
        if (ty > 0) {
            float* r = &red[((ty - 1) * PPB + tx) * (COG * 4)];
#pragma unroll
            for (int g = 0; g < COG; g++)
#pragma unroll
                for (int dy = 0; dy < 2; dy++)
#pragma unroll
                    for (int dx = 0; dx < 2; dx++)
                        r[g * 4 + dy * 2 + dx] = acc[g][dy][dx];
        }
        __syncthreads();
        if (ty > 0) return;
#pragma unroll
        for (int s = 0; s < S - 1; s++) {
            const float* r = &red[(s * PPB + tx) * (COG * 4)];
#pragma unroll
            for (int g = 0; g < COG; g++)
#pragma unroll
                for (int dy = 0; dy < 2; dy++)
#pragma unroll
                    for (int dx = 0; dx < 2; dx++)
                        acc[g][dy][dx] += r[g * 4 + dy * 2 + dx];
        }
    }

#pragma unroll
    for (int g = 0; g < COG; g++) {
        float b = bias[co0 + g];
        float a00 = leaky(acc[g][0][0] + b);
        float a01 = leaky(acc[g][0][1] + b);
        float a10 = leaky(acc[g][1][0] + b);
        float a11 = leaky(acc[g][1][1] + b);
        int coidx = n * CO + co0 + g;
        if (path2) {
            float* fp = f + (size_t)coidx * H * H;
            fp[(2 * py) * H + 2 * px] = a00;
            fp[(2 * py) * H + 2 * px + 1] = a01;
            fp[(2 * py + 1) * H + 2 * px] = a10;
            fp[(2 * py + 1) * H + 2 * px + 1] = a11;
        }
        pooled[((size_t)coidx * HP + py) * HP + px] = fmaxf(fmaxf(a00, a01), fmaxf(a10, a11));
    }
}

// ============ attention, all 4 levels in one kernel ============
template<int C, int HS, int SHIFT>
__device__ __forceinline__ void attn_level(const float* __restrict__ h2p,
                                           const float* __restrict__ h1p,
                                           const int* __restrict__ pts,
                                           float* __restrict__ attn,
                                           int b, int blk, float* qs, float* nqs) {
    constexpr int P = HS * HS;
    int tid = threadIdx.x;
    for (int i = tid; i < LL * C; i += blockDim.x) {
        int l = i / C, c = i % C;
        int qr = pts[(b * LL + l) * 2 + 0] >> SHIFT;
        int qc = pts[(b * LL + l) * 2 + 1] >> SHIFT;
        qs[l * C + c] = h1p[((size_t)(b * C + c)) * P + qr * HS + qc];
    }
    __syncthreads();
    if (tid < LL) {
        float s = 0.f;
#pragma unroll
        for (int c = 0; c < C; c++) s += qs[tid * C + c] * qs[tid * C + c];
        nqs[tid] = fmaxf(sqrtf(s), 1e-8f);
    }
    __syncthreads();

    int p0 = (blk * (int)blockDim.x + tid) * 4;
    if (p0 >= P) return;
    float4 v[C];
    float4 n2 = make_float4(0.f, 0.f, 0.f, 0.f);
#pragma unroll
    for (int c = 0; c < C; c++) {
        v[c] = *(const float4*)(h2p + ((size_t)(b * C + c)) * P + p0);
        n2.x += v[c].x * v[c].x; n2.y += v[c].y * v[c].y;
        n2.z += v[c].z * v[c].z; n2.w += v[c].w * v[c].w;
    }
    float4 inv;
    inv.x = 1.f / fmaxf(sqrtf(n2.x), 1e-8f);
    inv.y = 1.f / fmaxf(sqrtf(n2.y), 1e-8f);
    inv.z = 1.f / fmaxf(sqrtf(n2.z), 1e-8f);
    inv.w = 1.f / fmaxf(sqrtf(n2.w), 1e-8f);
#pragma unroll
    for (int l = 0; l < LL; l++) {
        float4 d = make_float4(0.f, 0.f, 0.f, 0.f);
#pragma unroll
        for (int c = 0; c < C; c++) {
            float q = qs[l * C + c];
            d.x += v[c].x * q; d.y += v[c].y * q;
            d.z += v[c].z * q; d.w += v[c].w * q;
        }
        float rq = 1.f / nqs[l];
        d.x *= inv.x * rq; d.y *= inv.y * rq; d.z *= inv.z * rq; d.w *= inv.w * rq;
        *(float4*)(attn + ((size_t)(b * LL + l)) * P + p0) = d;
    }
}

__global__ void attn_all_k(const float* __restrict__ h2p0, const float* __restrict__ h1p0,
                           const float* __restrict__ h2p1, const float* __restrict__ h1p1,
                           const float* __restrict__ h2p2, const float* __restrict__ h1p2,
                           const float* __restrict__ h2p3, const float* __restrict__ h1p3,
                           const int* __restrict__ pts,
                           float* __restrict__ a0, float* __restrict__ a1,
                           float* __restrict__ a2, float* __restrict__ a3) {
    __shared__ float qs[LL * 16];
    __shared__ float nqs[LL];
    int id = blockIdx.x;
    if (id < 32)      attn_level<4, 128, 1>(h2p0, h1p0, pts, a0, id / 16, id % 16, qs, nqs);
    else if (id < 40) attn_level<8, 64, 2>(h2p1, h1p1, pts, a1, (id - 32) / 4, (id - 32) % 4, qs, nqs);
    else if (id < 42) attn_level<16, 32, 3>(h2p2, h1p2, pts, a2, id - 40, 0, qs, nqs);
    else              attn_level<16, 16, 4>(h2p3, h1p3, pts, a3, id - 42, 0, qs, nqs);
}

// ============ fused decoder: balanced interleaved channel split across S ============
// Unified channel list: [0,CHALF) = half-res (h2 then attn), [CHALF,CIN) = full-res feat.
// Each ty handles channels c = ty, ty+S, ty+2S, ... (round-robin -> balanced).
template<int CH2, int CF, int CO, int COG, int HO, bool LEAKY, bool H2MOD, int S, int PPB>
__global__ void dec_conv5_t(const float* __restrict__ h2, const float* __restrict__ attn,
                            const float* __restrict__ feat, const float* __restrict__ w,
                            const float* __restrict__ bias, float* __restrict__ out) {
    constexpr int CIN = CH2 + 1 + CF;
    constexpr int CHALF = CH2 + 1;
    constexpr int HH = HO / 2;
    constexpr int NG = CO / COG;
    constexpr int NCH = (CIN + S - 1) / S;
    static_assert((HH * HH) % PPB == 0, "");
    __shared__ float ws[COG * CIN * 9];
    __shared__ float weff[COG * CHALF * 16];
    __shared__ float red[(S > 1) ? (S - 1) * PPB * COG * 4 : 1];

    int bly = blockIdx.y;
    int cog = bly % NG;
    int n = bly / NG;
    int co0 = cog * COG;
    int tx = threadIdx.x, ty = threadIdx.y;
    int tid = ty * PPB + tx;
    for (int i = tid; i < COG * CIN * 9; i += PPB * S)
        ws[i] = w[co0 * CIN * 9 + i];
    __syncthreads();
    for (int i = tid; i < COG * CHALF * 4; i += PPB * S) {
        int par = i & 3;
        int gc = i >> 2;
        int g = gc / CHALF, ch = gc % CHALF;
        float e[4];
        build_eff(&ws[(g * CIN + ch) * 9], par >> 1, par & 1, e);
        float* o = &weff[gc * 16 + par * 4];
        o[0] = e[0]; o[1] = e[1]; o[2] = e[2]; o[3] = e[3];
    }
    __syncthreads();

    int p = blockIdx.x * PPB + tx;
    int X = p % HH, Y = p / HH;
    int nh2 = H2MOD ? (n % BB) : n;
    int nf = n % BB;

    float acc[COG][2][2] = {};

    const float* hb = h2 + (size_t)nh2 * CH2 * HH * HH;
    const float* ab = attn + (size_t)n * HH * HH;
    const float* fb = feat + (size_t)nf * CF * HO * HO;

#pragma unroll
    for (int i = 0; i < NCH; i++) {
        int c = ty + i * S;
        if (c >= CIN) break;
        if (c < CHALF) {
            // ---- half-res channel via per-parity 2x2 effective kernels ----
            const float* src = (c < CH2) ? (hb + c * HH * HH) : ab;
            float v[3][3];
#pragma unroll
            for (int r = 0; r < 3; r++) {
                int hy = Y - 1 + r;
                bool oy = (unsigned)hy < (unsigned)HH;
#pragma unroll
                for (int cc = 0; cc < 3; cc++) {
                    int hx = X - 1 + cc;
                    v[r][cc] = (oy && (unsigned)hx < (unsigned)HH) ? __ldg(src + hy * HH + hx) : 0.f;
                }
            }
#pragma unroll
            for (int g = 0; g < COG; g++) {
                const float* wf = &weff[(g * CHALF + c) * 16];
#pragma unroll
                for (int dy = 0; dy < 2; dy++)
#pragma unroll
                    for (int dx = 0; dx < 2; dx++)
#pragma unroll
                        for (int a = 0; a < 2; a++)
#pragma unroll
                            for (int b = 0; b < 2; b++)
                                acc[g][dy][dx] += v[((dy + 1) >> 1) + a][((dx + 1) >> 1) + b]
                                                  * wf[(dy * 2 + dx) * 4 + a * 2 + b];
            }
        } else {
            // ---- full-res feat channel ----
            int cf = c - CHALF;
            const float* src = fb + cf * HO * HO;
            float v[4][4];
#pragma unroll
            for (int r = 0; r < 4; r++) {
                int yy = 2 * Y - 1 + r;
                bool oy = (unsigned)yy < (unsigned)HO;
#pragma unroll
                for (int cc = 0; cc < 4; cc++) {
                    int xx = 2 * X - 1 + cc;
                    v[r][cc] = (oy && (unsigned)xx < (unsigned)HO) ? __ldg(src + yy * HO + xx) : 0.f;
                }
            }
#pragma unroll
            for (int g = 0; g < COG; g++)
#pragma unroll
                for (int dy = 0; dy < 2; dy++)
#pragma unroll
                    for (int dx = 0; dx < 2; dx++)
#pragma unroll
                        for (int ky = 0; ky < 3; ky++)
#pragma unroll
                            for (int kx = 0; kx < 3; kx++)
                                acc[g][dy][dx] += v[dy + ky][dx + kx]
                                                  * ws[(g * CIN + CHALF + cf) * 9 + ky * 3 + kx];
        }
    }

    if constexpr (S > 1) {
        if (ty > 0) {
            float* r = &red[((ty - 1) * PPB + tx) * (COG * 4)];
#pragma unroll
            for (int g = 0; g < COG; g++)
#pragma unroll
                for (int dy = 0; dy < 2; dy++)
#pragma unroll
                    for (int dx = 0; dx < 2; dx++)
                        r[g * 4 + dy * 2 + dx] = acc[g][dy][dx];
        }
        __syncthreads();
        if (ty > 0) return;
#pragma unroll
        for (int s = 0; s < S - 1; s++) {
            const float* r = &red[(s * PPB + tx) * (COG * 4)];
#pragma unroll
            for (int g = 0; g < COG; g++)
#pragma unroll
                for (int dy = 0; dy < 2; dy++)
#pragma unroll
                    for (int dx = 0; dx < 2; dx++)
                        acc[g][dy][dx] += r[g * 4 + dy * 2 + dx];
        }
    }

#pragma unroll
    for (int g = 0; g < COG; g++) {
        float b = bias[co0 + g];
#pragma unroll
        for (int dy = 0; dy < 2; dy++)
#pragma unroll
            for (int dx = 0; dx < 2; dx++) {
                float r = acc[g][dy][dx] + b;
                if (LEAKY) r = leaky(r);
                out[(((size_t)n * CO + co0 + g) * HO + 2 * Y + dy) * HO + 2 * X + dx] = r;
            }
    }
}

// ============ final decoder layer: CO=1, 4x4 output patch, eff-kernel half-res ============
template<int CH2, int CF, int HO, bool LEAKY>
__global__ void dec_conv_p4_t(const float* __restrict__ h2, const float* __restrict__ attn,
                              const float* __restrict__ feat, const float* __restrict__ w,
                              const float* __restrict__ bias, float* __restrict__ out) {
    constexpr int CIN = CH2 + 1 + CF;
    constexpr int CHALF = CH2 + 1;
    constexpr int HH = HO / 2;
    constexpr int QH = HO / 4;
    __shared__ float ws[CIN * 9];
    __shared__ float weff[CHALF * 16];
    int n = blockIdx.y;
    int tid = threadIdx.x;
    for (int i = tid; i < CIN * 9; i += blockDim.x) ws[i] = w[i];
    __syncthreads();
    for (int i = tid; i < CHALF * 4; i += blockDim.x) {
        int par = i & 3, ch = i >> 2;
        float e[4];
        build_eff(&ws[ch * 9], par >> 1, par & 1, e);
        float* o = &weff[ch * 16 + par * 4];
        o[0] = e[0]; o[1] = e[1]; o[2] = e[2]; o[3] = e[3];
    }
    __syncthreads();

    int p = blockIdx.x * blockDim.x + tid;
    int X = p % QH, Y = p / QH;
    int nf = n % BB;

    float acc[4][4] = {};

    // half-res channels: 4x4 halo at rows 2Y-1..2Y+2
    {
        const float* hb = h2 + (size_t)n * CH2 * HH * HH;
        const float* ab = attn + (size_t)n * HH * HH;
#pragma unroll
        for (int ch = 0; ch < CHALF; ch++) {
            const float* src = (ch < CH2) ? (hb + ch * HH * HH) : ab;
            float v[4][4];
#pragma unroll
            for (int r = 0; r < 4; r++) {
                int hy = 2 * Y - 1 + r;
                bool oy = (unsigned)hy < (unsigned)HH;
#pragma unroll
                for (int c = 0; c < 4; c++) {
                    int hx = 2 * X - 1 + c;
                    v[r][c] = (oy && (unsigned)hx < (unsigned)HH) ? __ldg(src + hy * HH + hx) : 0.f;
                }
            }
            const float* wf = &weff[ch * 16];
#pragma unroll
            for (int dy = 0; dy < 4; dy++)
#pragma unroll
                for (int dx = 0; dx < 4; dx++)
#pragma unroll
                    for (int a = 0; a < 2; a++)
#pragma unroll
                        for (int b = 0; b < 2; b++)
                            acc[dy][dx] += v[((dy + 1) >> 1) + a][((dx + 1) >> 1) + b]
                                           * wf[((dy & 1) * 2 + (dx & 1)) * 4 + a * 2 + b];
        }
    }

    // full-res feat channels: 6x6 halo at rows 4Y-1..4Y+4
    {
        const float* fb = feat + (size_t)nf * CF * HO * HO;
#pragma unroll
        for (int cf = 0; cf < CF; cf++) {
            const float* src = fb + cf * HO * HO;
            float v[6][6];
#pragma unroll
            for (int r = 0; r < 6; r++) {
                int yy = 4 * Y - 1 + r;
                bool oy = (unsigned)yy < (unsigned)HO;
#pragma unroll
                for (int c = 0; c < 6; c++) {
                    int xx = 4 * X - 1 + c;
                    v[r][c] = (oy && (unsigned)xx < (unsigned)HO) ? __ldg(src + yy * HO + xx) : 0.f;
                }
            }
            const float* wk = &ws[(CHALF + cf) * 9];
#pragma unroll
            for (int dy = 0; dy < 4; dy++)
#pragma unroll
                for (int dx = 0; dx < 4; dx++)
#pragma unroll
                    for (int ky = 0; ky < 3; ky++)
#pragma unroll
                        for (int kx = 0; kx < 3; kx++)
                            acc[dy][dx] += v[dy + ky][dx + kx] * wk[ky * 3 + kx];
        }
    }

    float b = bias[0];
#pragma unroll
    for (int dy = 0; dy < 4; dy++)
#pragma unroll
        for (int dx = 0; dx < 4; dx++) {
            float r = acc[dy][dx] + b;
            if (LEAKY) r = leaky(r);
            out[((size_t)n * HO + 4 * Y + dy) * HO + 4 * X + dx] = r;
        }
}

// ---------------- launch ----------------
extern "C" void kernel_launch(void* const* d_in, const int* in_sizes, int n_in,
                              void* d_out, int out_size) {
    const float* x1 = (const float*)d_in[0];
    const float* x2 = (const float*)d_in[1];
    const int* pts = (const int*)d_in[2];
    const float* ew[4] = {(const float*)d_in[3], (const float*)d_in[5],
                          (const float*)d_in[7], (const float*)d_in[9]};
    const float* eb[4] = {(const float*)d_in[4], (const float*)d_in[6],
                          (const float*)d_in[8], (const float*)d_in[10]};
    const float* dw[4] = {(const float*)d_in[11], (const float*)d_in[13],
                          (const float*)d_in[15], (const float*)d_in[17]};
    const float* db[4] = {(const float*)d_in[12], (const float*)d_in[14],
                          (const float*)d_in[16], (const float*)d_in[18]};
    float* out = (float*)d_out;

    float *h1p0, *h1p1, *h1p2, *h1p3;
    float *f0, *f1, *f2, *f3;
    float *h2p0, *h2p1, *h2p2, *h2p3;
    float *a0, *a1, *a2, *a3;
    float *dd0, *dd1, *dd2;
    cudaGetSymbolAddress((void**)&h1p0, g_h1p0);
    cudaGetSymbolAddress((void**)&h1p1, g_h1p1);
    cudaGetSymbolAddress((void**)&h1p2, g_h1p2);
    cudaGetSymbolAddress((void**)&h1p3, g_h1p3);
    cudaGetSymbolAddress((void**)&f0, g_f0);
    cudaGetSymbolAddress((void**)&f1, g_f1);
    cudaGetSymbolAddress((void**)&f2, g_f2);
    cudaGetSymbolAddress((void**)&f3, g_f3);
    cudaGetSymbolAddress((void**)&h2p0, g_h2p0);
    cudaGetSymbolAddress((void**)&h2p1, g_h2p1);
    cudaGetSymbolAddress((void**)&h2p2, g_h2p2);
    cudaGetSymbolAddress((void**)&h2p3, g_h2p3);
    cudaGetSymbolAddress((void**)&a0, g_attn0);
    cudaGetSymbolAddress((void**)&a1, g_attn1);
    cudaGetSymbolAddress((void**)&a2, g_attn2);
    cudaGetSymbolAddress((void**)&a3, g_attn3);
    cudaGetSymbolAddress((void**)&dd0, g_d0);
    cudaGetSymbolAddress((void**)&dd1, g_d1);
    cudaGetSymbolAddress((void**)&dd2, g_d2);

    // ---- encoder chain: deep ci-splits for occupancy ----
    enc_conv3_t<3, 4, 4, 256, 3, 128><<<dim3(128, 2, 2), dim3(128, 3)>>>(x2, x1, ew[0], eb[0], f0, h2p0, h1p0);
    enc_conv3_t<4, 8, 4, 128, 4, 64><<<dim3(64, 4, 2), dim3(64, 4)>>>(h2p0, h1p0, ew[1], eb[1], f1, h2p1, h1p1);
    enc_conv3_t<8, 16, 2, 64, 4, 32><<<dim3(32, 16, 2), dim3(32, 4)>>>(h2p1, h1p1, ew[2], eb[2], f2, h2p2, h1p2);
    enc_conv3_t<16, 16, 2, 32, 8, 32><<<dim3(8, 16, 2), dim3(32, 8)>>>(h2p2, h1p2, ew[3], eb[3], f3, h2p3, h1p3);

    // ---- all attention levels in one kernel ----
    attn_all_k<<<44, 256>>>(h2p0, h1p0, h2p1, h1p1, h2p2, h1p2, h2p3, h1p3,
                            pts, a0, a1, a2, a3);

    // ---- decoder: balanced 4-way interleaved channel split ----
    dec_conv5_t<16, 16, 16, 8, 32, true, true, 4, 32><<<dim3(8, 128), dim3(32, 4)>>>(h2p3, a3, f3, dw[0], db[0], dd0);
    dec_conv5_t<16, 16, 8, 8, 64, true, false, 4, 64><<<dim3(16, 64), dim3(64, 4)>>>(dd0, a2, f2, dw[1], db[1], dd1);
    dec_conv5_t<8, 8, 4, 4, 128, true, false, 4, 64><<<dim3(64, 64), dim3(64, 4)>>>(dd1, a1, f1, dw[2], db[2], dd2);
    dec_conv_p4_t<4, 4, 256, false><<<dim3(32, 64), 128>>>(dd2, a0, f0, dw[3], db[3], out);
}

// round 9
// speedup vs baseline: 1.0501x; 1.0501x over previous
#include <cuda_runtime.h>
#include <math.h>

#define BB 2
#define LL 32
#define NSLOPE 0.01f

// ---------------- scratch (static __device__, no allocs) ----------------
__device__ float g_h1p0[2*4*128*128];
__device__ float g_h1p1[2*8*64*64];
__device__ float g_h1p2[2*16*32*32];
__device__ float g_h1p3[2*16*16*16];

__device__ float g_f0[2*4*256*256];
__device__ float g_f1[2*8*128*128];
__device__ float g_f2[2*16*64*64];
__device__ float g_f3[2*16*32*32];

__device__ float g_h2p0[2*4*128*128];
__device__ float g_h2p1[2*8*64*64];
__device__ float g_h2p2[2*16*32*32];
__device__ float g_h2p3[2*16*16*16];

__device__ float g_attn0[64*128*128];
__device__ float g_attn1[64*64*64];
__device__ float g_attn2[64*32*32];
__device__ float g_attn3[64*16*16];

__device__ float g_d0[64*16*32*32];
__device__ float g_d1[64*8*64*64];
__device__ float g_d2[64*4*128*128];

static inline int cdiv(int a, int b) { return (a + b - 1) / b; }

__device__ __forceinline__ float leaky(float v) { return v >= 0.f ? v : NSLOPE * v; }

// Build per-parity 2x2 effective kernel from a 3x3 kernel (upsample-nearest folding).
__device__ __forceinline__ void build_eff(const float* wk, int ey, int ex, float* e) {
    float rs[2][3];
    if (ey == 0) {
        rs[0][0] = wk[0]; rs[0][1] = wk[1]; rs[0][2] = wk[2];
        rs[1][0] = wk[3] + wk[6]; rs[1][1] = wk[4] + wk[7]; rs[1][2] = wk[5] + wk[8];
    } else {
        rs[0][0] = wk[0] + wk[3]; rs[0][1] = wk[1] + wk[4]; rs[0][2] = wk[2] + wk[5];
        rs[1][0] = wk[6]; rs[1][1] = wk[7]; rs[1][2] = wk[8];
    }
#pragma unroll
    for (int a = 0; a < 2; a++) {
        if (ex == 0) { e[a * 2 + 0] = rs[a][0]; e[a * 2 + 1] = rs[a][1] + rs[a][2]; }
        else         { e[a * 2 + 0] = rs[a][0] + rs[a][1]; e[a * 2 + 1] = rs[a][2]; }
    }
}

// ============ encoder: conv5x5+leaky[+feats]+maxpool2, ci-split S, both paths (z) ============
template<int CI, int CO, int COG, int H, int S, int PPB>
__global__ void enc_conv3_t(const float* __restrict__ in2, const float* __restrict__ in1,
                            const float* __restrict__ w, const float* __restrict__ bias,
                            float* __restrict__ f, float* __restrict__ pooled2,
                            float* __restrict__ pooled1) {
    constexpr int HP = H / 2;
    constexpr int NG = CO / COG;
    constexpr int CIG = CI / S;
    static_assert(CI % S == 0, "");
    static_assert((HP * HP) % PPB == 0, "");
    __shared__ float ws[COG * CI * 25];
    __shared__ float red[(S > 1) ? (S - 1) * PPB * COG * 4 : 1];

    int bly = blockIdx.y;
    int cog = bly % NG;
    int n = bly / NG;
    int co0 = cog * COG;
    bool path2 = (blockIdx.z == 0);
    const float* in = path2 ? in2 : in1;
    float* pooled = path2 ? pooled2 : pooled1;

    int tx = threadIdx.x, ty = threadIdx.y;
    int tid = ty * PPB + tx;
    for (int i = tid; i < COG * CI * 25; i += PPB * S)
        ws[i] = w[co0 * CI * 25 + i];
    __syncthreads();

    int p = blockIdx.x * PPB + tx;
    int px = p % HP, py = p / HP;

    float acc[COG][2][2] = {};

    const float* ib = in + (size_t)n * CI * H * H;
#pragma unroll
    for (int i = 0; i < CIG; i++) {
        int ci = ty * CIG + i;
        const float* src = ib + ci * H * H;
        float v[6][6];
#pragma unroll
        for (int r = 0; r < 6; r++) {
            int yy = 2 * py - 2 + r;
            bool oy = (unsigned)yy < (unsigned)H;
#pragma unroll
            for (int c = 0; c < 6; c++) {
                int xx = 2 * px - 2 + c;
                v[r][c] = (oy && (unsigned)xx < (unsigned)H) ? __ldg(src + yy * H + xx) : 0.f;
            }
        }
#pragma unroll
        for (int g = 0; g < COG; g++)
#pragma unroll
            for (int dy = 0; dy < 2; dy++)
#pragma unroll
                for (int dx = 0; dx < 2; dx++)
#pragma unroll
                    for (int ky = 0; ky < 5; ky++)
#pragma unroll
                        for (int kx = 0; kx < 5; kx++)
                            acc[g][dy][dx] += v[dy + ky][dx + kx] * ws[(g * CI + ci) * 25 + ky * 5 + kx];
    }

    if constexpr (S > 1) {
        if (ty > 0) {
            float* r = &red[((ty - 1) * PPB + tx) * (COG * 4)];
#pragma unroll
            for (int g = 0; g < COG; g++)
#pragma unroll
                for (int dy = 0; dy < 2; dy++)
#pragma unroll
                    for (int dx = 0; dx < 2; dx++)
                        r[g * 4 + dy * 2 + dx] = acc[g][dy][dx];
        }
        __syncthreads();
        if (ty > 0) return;
#pragma unroll
        for (int s = 0; s < S - 1; s++) {
            const float* r = &red[(s * PPB + tx) * (COG * 4)];
#pragma unroll
            for (int g = 0; g < COG; g++)
#pragma unroll
                for (int dy = 0; dy < 2; dy++)
#pragma unroll
                    for (int dx = 0; dx < 2; dx++)
                        acc[g][dy][dx] += r[g * 4 + dy * 2 + dx];
        }
    }

#pragma unroll
    for (int g = 0; g < COG; g++) {
        float b = bias[co0 + g];
        float a00 = leaky(acc[g][0][0] + b);
        float a01 = leaky(acc[g][0][1] + b);
        float a10 = leaky(acc[g][1][0] + b);
        float a11 = leaky(acc[g][1][1] + b);
        int coidx = n * CO + co0 + g;
        if (path2) {
            float* fp = f + (size_t)coidx * H * H;
            fp[(2 * py) * H + 2 * px] = a00;
            fp[(2 * py) * H + 2 * px + 1] = a01;
            fp[(2 * py + 1) * H + 2 * px] = a10;
            fp[(2 * py + 1) * H + 2 * px + 1] = a11;
        }
        pooled[((size_t)coidx * HP + py) * HP + px] = fmaxf(fmaxf(a00, a01), fmaxf(a10, a11));
    }
}

// ============ attention, all 4 levels in one kernel ============
template<int C, int HS, int SHIFT>
__device__ __forceinline__ void attn_level(const float* __restrict__ h2p,
                                           const float* __restrict__ h1p,
                                           const int* __restrict__ pts,
                                           float* __restrict__ attn,
                                           int b, int blk, float* qs, float* nqs) {
    constexpr int P = HS * HS;
    int tid = threadIdx.x;
    for (int i = tid; i < LL * C; i += blockDim.x) {
        int l = i / C, c = i % C;
        int qr = pts[(b * LL + l) * 2 + 0] >> SHIFT;
        int qc = pts[(b * LL + l) * 2 + 1] >> SHIFT;
        qs[l * C + c] = h1p[((size_t)(b * C + c)) * P + qr * HS + qc];
    }
    __syncthreads();
    if (tid < LL) {
        float s = 0.f;
#pragma unroll
        for (int c = 0; c < C; c++) s += qs[tid * C + c] * qs[tid * C + c];
        nqs[tid] = fmaxf(sqrtf(s), 1e-8f);
    }
    __syncthreads();

    int p0 = (blk * (int)blockDim.x + tid) * 4;
    if (p0 >= P) return;
    float4 v[C];
    float4 n2 = make_float4(0.f, 0.f, 0.f, 0.f);
#pragma unroll
    for (int c = 0; c < C; c++) {
        v[c] = *(const float4*)(h2p + ((size_t)(b * C + c)) * P + p0);
        n2.x += v[c].x * v[c].x; n2.y += v[c].y * v[c].y;
        n2.z += v[c].z * v[c].z; n2.w += v[c].w * v[c].w;
    }
    float4 inv;
    inv.x = 1.f / fmaxf(sqrtf(n2.x), 1e-8f);
    inv.y = 1.f / fmaxf(sqrtf(n2.y), 1e-8f);
    inv.z = 1.f / fmaxf(sqrtf(n2.z), 1e-8f);
    inv.w = 1.f / fmaxf(sqrtf(n2.w), 1e-8f);
#pragma unroll
    for (int l = 0; l < LL; l++) {
        float4 d = make_float4(0.f, 0.f, 0.f, 0.f);
#pragma unroll
        for (int c = 0; c < C; c++) {
            float q = qs[l * C + c];
            d.x += v[c].x * q; d.y += v[c].y * q;
            d.z += v[c].z * q; d.w += v[c].w * q;
        }
        float rq = 1.f / nqs[l];
        d.x *= inv.x * rq; d.y *= inv.y * rq; d.z *= inv.z * rq; d.w *= inv.w * rq;
        *(float4*)(attn + ((size_t)(b * LL + l)) * P + p0) = d;
    }
}

__global__ void attn_all_k(const float* __restrict__ h2p0, const float* __restrict__ h1p0,
                           const float* __restrict__ h2p1, const float* __restrict__ h1p1,
                           const float* __restrict__ h2p2, const float* __restrict__ h1p2,
                           const float* __restrict__ h2p3, const float* __restrict__ h1p3,
                           const int* __restrict__ pts,
                           float* __restrict__ a0, float* __restrict__ a1,
                           float* __restrict__ a2, float* __restrict__ a3) {
    __shared__ float qs[LL * 16];
    __shared__ float nqs[LL];
    int id = blockIdx.x;
    if (id < 32)      attn_level<4, 128, 1>(h2p0, h1p0, pts, a0, id / 16, id % 16, qs, nqs);
    else if (id < 40) attn_level<8, 64, 2>(h2p1, h1p1, pts, a1, (id - 32) / 4, (id - 32) % 4, qs, nqs);
    else if (id < 42) attn_level<16, 32, 3>(h2p2, h1p2, pts, a2, id - 40, 0, qs, nqs);
    else              attn_level<16, 16, 4>(h2p3, h1p3, pts, a3, id - 42, 0, qs, nqs);
}

// ============ fused decoder: 3-way ROLE-STATIC split ============
// ty=0: all CHALF half-res channels (eff kernels, 17*4=68 FMA-units)
// ty=1: feat channels [0, CF/2)           (CF/2*9 FMA-units)
// ty=2: feat channels [CF/2, CF)          (CF/2*9 FMA-units)
template<int CH2, int CF, int CO, int COG, int HO, bool LEAKY, bool H2MOD, int PPB>
__global__ void dec_conv6_t(const float* __restrict__ h2, const float* __restrict__ attn,
                            const float* __restrict__ feat, const float* __restrict__ w,
                            const float* __restrict__ bias, float* __restrict__ out) {
    constexpr int S = 3;
    constexpr int CIN = CH2 + 1 + CF;
    constexpr int CHALF = CH2 + 1;
    constexpr int CFH = CF / 2;
    constexpr int HH = HO / 2;
    constexpr int NG = CO / COG;
    static_assert(CF % 2 == 0, "");
    static_assert((HH * HH) % PPB == 0, "");
    __shared__ float ws[COG * CIN * 9];
    __shared__ float weff[COG * CHALF * 16];
    __shared__ float red[(S - 1) * PPB * COG * 4];

    int bly = blockIdx.y;
    int cog = bly % NG;
    int n = bly / NG;
    int co0 = cog * COG;
    int tx = threadIdx.x, ty = threadIdx.y;
    int tid = ty * PPB + tx;
    for (int i = tid; i < COG * CIN * 9; i += PPB * S)
        ws[i] = w[co0 * CIN * 9 + i];
    __syncthreads();
    for (int i = tid; i < COG * CHALF * 4; i += PPB * S) {
        int par = i & 3;
        int gc = i >> 2;
        int g = gc / CHALF, ch = gc % CHALF;
        float e[4];
        build_eff(&ws[(g * CIN + ch) * 9], par >> 1, par & 1, e);
        float* o = &weff[gc * 16 + par * 4];
        o[0] = e[0]; o[1] = e[1]; o[2] = e[2]; o[3] = e[3];
    }
    __syncthreads();

    int p = blockIdx.x * PPB + tx;
    int X = p % HH, Y = p / HH;
    int nh2 = H2MOD ? (n % BB) : n;
    int nf = n % BB;

    float acc[COG][2][2] = {};

    if (ty == 0) {
        // ---- half-res channels (h2 then attn) via per-parity 2x2 effective kernels ----
        const float* hb = h2 + (size_t)nh2 * CH2 * HH * HH;
        const float* ab = attn + (size_t)n * HH * HH;
#pragma unroll 4
        for (int ch = 0; ch < CHALF; ch++) {
            const float* src = (ch < CH2) ? (hb + ch * HH * HH) : ab;
            float v[3][3];
#pragma unroll
            for (int r = 0; r < 3; r++) {
                int hy = Y - 1 + r;
                bool oy = (unsigned)hy < (unsigned)HH;
#pragma unroll
                for (int c = 0; c < 3; c++) {
                    int hx = X - 1 + c;
                    v[r][c] = (oy && (unsigned)hx < (unsigned)HH) ? __ldg(src + hy * HH + hx) : 0.f;
                }
            }
#pragma unroll
            for (int g = 0; g < COG; g++) {
                const float* wf = &weff[(g * CHALF + ch) * 16];
#pragma unroll
                for (int dy = 0; dy < 2; dy++)
#pragma unroll
                    for (int dx = 0; dx < 2; dx++)
#pragma unroll
                        for (int a = 0; a < 2; a++)
#pragma unroll
                            for (int b = 0; b < 2; b++)
                                acc[g][dy][dx] += v[((dy + 1) >> 1) + a][((dx + 1) >> 1) + b]
                                                  * wf[(dy * 2 + dx) * 4 + a * 2 + b];
            }
        }
    } else {
        // ---- full-res feat channel slice ----
        int cf0 = (ty - 1) * CFH;
        const float* fb = feat + (size_t)nf * CF * HO * HO;
#pragma unroll 4
        for (int i = 0; i < CFH; i++) {
            int cf = cf0 + i;
            const float* src = fb + cf * HO * HO;
            float v[4][4];
#pragma unroll
            for (int r = 0; r < 4; r++) {
                int yy = 2 * Y - 1 + r;
                bool oy = (unsigned)yy < (unsigned)HO;
#pragma unroll
                for (int c = 0; c < 4; c++) {
                    int xx = 2 * X - 1 + c;
                    v[r][c] = (oy && (unsigned)xx < (unsigned)HO) ? __ldg(src + yy * HO + xx) : 0.f;
                }
            }
#pragma unroll
            for (int g = 0; g < COG; g++)
#pragma unroll
                for (int dy = 0; dy < 2; dy++)
#pragma unroll
                    for (int dx = 0; dx < 2; dx++)
#pragma unroll
                        for (int ky = 0; ky < 3; ky++)
#pragma unroll
                            for (int kx = 0; kx < 3; kx++)
                                acc[g][dy][dx] += v[dy + ky][dx + kx]
                                                  * ws[(g * CIN + CH2 + 1 + cf) * 9 + ky * 3 + kx];
        }
    }

    // reduction
    if (ty > 0) {
        float* r = &red[((ty - 1) * PPB + tx) * (COG * 4)];
#pragma unroll
        for (int g = 0; g < COG; g++)
#pragma unroll
            for (int dy = 0; dy < 2; dy++)
#pragma unroll
                for (int dx = 0; dx < 2; dx++)
                    r[g * 4 + dy * 2 + dx] = acc[g][dy][dx];
    }
    __syncthreads();
    if (ty > 0) return;
#pragma unroll
    for (int s = 0; s < S - 1; s++) {
        const float* r = &red[(s * PPB + tx) * (COG * 4)];
#pragma unroll
        for (int g = 0; g < COG; g++)
#pragma unroll
            for (int dy = 0; dy < 2; dy++)
#pragma unroll
                for (int dx = 0; dx < 2; dx++)
                    acc[g][dy][dx] += r[g * 4 + dy * 2 + dx];
    }

#pragma unroll
    for (int g = 0; g < COG; g++) {
        float b = bias[co0 + g];
#pragma unroll
        for (int dy = 0; dy < 2; dy++)
#pragma unroll
            for (int dx = 0; dx < 2; dx++) {
                float r = acc[g][dy][dx] + b;
                if (LEAKY) r = leaky(r);
                out[(((size_t)n * CO + co0 + g) * HO + 2 * Y + dy) * HO + 2 * X + dx] = r;
            }
    }
}

// ============ final decoder layer: CO=1, 4x4 output patch, eff-kernel half-res ============
template<int CH2, int CF, int HO, bool LEAKY>
__global__ void dec_conv_p4_t(const float* __restrict__ h2, const float* __restrict__ attn,
                              const float* __restrict__ feat, const float* __restrict__ w,
                              const float* __restrict__ bias, float* __restrict__ out) {
    constexpr int CIN = CH2 + 1 + CF;
    constexpr int CHALF = CH2 + 1;
    constexpr int HH = HO / 2;
    constexpr int QH = HO / 4;
    __shared__ float ws[CIN * 9];
    __shared__ float weff[CHALF * 16];
    int n = blockIdx.y;
    int tid = threadIdx.x;
    for (int i = tid; i < CIN * 9; i += blockDim.x) ws[i] = w[i];
    __syncthreads();
    for (int i = tid; i < CHALF * 4; i += blockDim.x) {
        int par = i & 3, ch = i >> 2;
        float e[4];
        build_eff(&ws[ch * 9], par >> 1, par & 1, e);
        float* o = &weff[ch * 16 + par * 4];
        o[0] = e[0]; o[1] = e[1]; o[2] = e[2]; o[3] = e[3];
    }
    __syncthreads();

    int p = blockIdx.x * blockDim.x + tid;
    int X = p % QH, Y = p / QH;
    int nf = n % BB;

    float acc[4][4] = {};

    // half-res channels: 4x4 halo at rows 2Y-1..2Y+2
    {
        const float* hb = h2 + (size_t)n * CH2 * HH * HH;
        const float* ab = attn + (size_t)n * HH * HH;
#pragma unroll
        for (int ch = 0; ch < CHALF; ch++) {
            const float* src = (ch < CH2) ? (hb + ch * HH * HH) : ab;
            float v[4][4];
#pragma unroll
            for (int r = 0; r < 4; r++) {
                int hy = 2 * Y - 1 + r;
                bool oy = (unsigned)hy < (unsigned)HH;
#pragma unroll
                for (int c = 0; c < 4; c++) {
                    int hx = 2 * X - 1 + c;
                    v[r][c] = (oy && (unsigned)hx < (unsigned)HH) ? __ldg(src + hy * HH + hx) : 0.f;
                }
            }
            const float* wf = &weff[ch * 16];
#pragma unroll
            for (int dy = 0; dy < 4; dy++)
#pragma unroll
                for (int dx = 0; dx < 4; dx++)
#pragma unroll
                    for (int a = 0; a < 2; a++)
#pragma unroll
                        for (int b = 0; b < 2; b++)
                            acc[dy][dx] += v[((dy + 1) >> 1) + a][((dx + 1) >> 1) + b]
                                           * wf[((dy & 1) * 2 + (dx & 1)) * 4 + a * 2 + b];
        }
    }

    // full-res feat channels: 6x6 halo at rows 4Y-1..4Y+4
    {
        const float* fb = feat + (size_t)nf * CF * HO * HO;
#pragma unroll
        for (int cf = 0; cf < CF; cf++) {
            const float* src = fb + cf * HO * HO;
            float v[6][6];
#pragma unroll
            for (int r = 0; r < 6; r++) {
                int yy = 4 * Y - 1 + r;
                bool oy = (unsigned)yy < (unsigned)HO;
#pragma unroll
                for (int c = 0; c < 6; c++) {
                    int xx = 4 * X - 1 + c;
                    v[r][c] = (oy && (unsigned)xx < (unsigned)HO) ? __ldg(src + yy * HO + xx) : 0.f;
                }
            }
            const float* wk = &ws[(CHALF + cf) * 9];
#pragma unroll
            for (int dy = 0; dy < 4; dy++)
#pragma unroll
                for (int dx = 0; dx < 4; dx++)
#pragma unroll
                    for (int ky = 0; ky < 3; ky++)
#pragma unroll
                        for (int kx = 0; kx < 3; kx++)
                            acc[dy][dx] += v[dy + ky][dx + kx] * wk[ky * 3 + kx];
        }
    }

    float b = bias[0];
#pragma unroll
    for (int dy = 0; dy < 4; dy++)
#pragma unroll
        for (int dx = 0; dx < 4; dx++) {
            float r = acc[dy][dx] + b;
            if (LEAKY) r = leaky(r);
            out[((size_t)n * HO + 4 * Y + dy) * HO + 4 * X + dx] = r;
        }
}

// ---------------- launch ----------------
extern "C" void kernel_launch(void* const* d_in, const int* in_sizes, int n_in,
                              void* d_out, int out_size) {
    const float* x1 = (const float*)d_in[0];
    const float* x2 = (const float*)d_in[1];
    const int* pts = (const int*)d_in[2];
    const float* ew[4] = {(const float*)d_in[3], (const float*)d_in[5],
                          (const float*)d_in[7], (const float*)d_in[9]};
    const float* eb[4] = {(const float*)d_in[4], (const float*)d_in[6],
                          (const float*)d_in[8], (const float*)d_in[10]};
    const float* dw[4] = {(const float*)d_in[11], (const float*)d_in[13],
                          (const float*)d_in[15], (const float*)d_in[17]};
    const float* db[4] = {(const float*)d_in[12], (const float*)d_in[14],
                          (const float*)d_in[16], (const float*)d_in[18]};
    float* out = (float*)d_out;

    float *h1p0, *h1p1, *h1p2, *h1p3;
    float *f0, *f1, *f2, *f3;
    float *h2p0, *h2p1, *h2p2, *h2p3;
    float *a0, *a1, *a2, *a3;
    float *dd0, *dd1, *dd2;
    cudaGetSymbolAddress((void**)&h1p0, g_h1p0);
    cudaGetSymbolAddress((void**)&h1p1, g_h1p1);
    cudaGetSymbolAddress((void**)&h1p2, g_h1p2);
    cudaGetSymbolAddress((void**)&h1p3, g_h1p3);
    cudaGetSymbolAddress((void**)&f0, g_f0);
    cudaGetSymbolAddress((void**)&f1, g_f1);
    cudaGetSymbolAddress((void**)&f2, g_f2);
    cudaGetSymbolAddress((void**)&f3, g_f3);
    cudaGetSymbolAddress((void**)&h2p0, g_h2p0);
    cudaGetSymbolAddress((void**)&h2p1, g_h2p1);
    cudaGetSymbolAddress((void**)&h2p2, g_h2p2);
    cudaGetSymbolAddress((void**)&h2p3, g_h2p3);
    cudaGetSymbolAddress((void**)&a0, g_attn0);
    cudaGetSymbolAddress((void**)&a1, g_attn1);
    cudaGetSymbolAddress((void**)&a2, g_attn2);
    cudaGetSymbolAddress((void**)&a3, g_attn3);
    cudaGetSymbolAddress((void**)&dd0, g_d0);
    cudaGetSymbolAddress((void**)&dd1, g_d1);
    cudaGetSymbolAddress((void**)&dd2, g_d2);

    // ---- encoder chain: R6 shallow levels + R8 deep-split levels ----
    enc_conv3_t<3, 4, 4, 256, 1, 128><<<dim3(128, 2, 2), dim3(128, 1)>>>(x2, x1, ew[0], eb[0], f0, h2p0, h1p0);
    enc_conv3_t<4, 8, 4, 128, 2, 64><<<dim3(64, 4, 2), dim3(64, 2)>>>(h2p0, h1p0, ew[1], eb[1], f1, h2p1, h1p1);
    enc_conv3_t<8, 16, 2, 64, 4, 32><<<dim3(32, 16, 2), dim3(32, 4)>>>(h2p1, h1p1, ew[2], eb[2], f2, h2p2, h1p2);
    enc_conv3_t<16, 16, 2, 32, 8, 32><<<dim3(8, 16, 2), dim3(32, 8)>>>(h2p2, h1p2, ew[3], eb[3], f3, h2p3, h1p3);

    // ---- all attention levels in one kernel ----
    attn_all_k<<<44, 256>>>(h2p0, h1p0, h2p1, h1p1, h2p2, h1p2, h2p3, h1p3,
                            pts, a0, a1, a2, a3);

    // ---- decoder: role-static 3-way split (half | feat-lo | feat-hi) ----
    dec_conv6_t<16, 16, 16, 8, 32, true, true, 64><<<dim3(4, 128), dim3(64, 3)>>>(h2p3, a3, f3, dw[0], db[0], dd0);
    dec_conv6_t<16, 16, 8, 8, 64, true, false, 64><<<dim3(16, 64), dim3(64, 3)>>>(dd0, a2, f2, dw[1], db[1], dd1);
    dec_conv6_t<8, 8, 4, 4, 128, true, false, 64><<<dim3(64, 64), dim3(64, 3)>>>(dd1, a1, f1, dw[2], db[2], dd2);
    dec_conv_p4_t<4, 4, 256, false><<<dim3(32, 64), 128>>>(dd2, a0, f0, dw[3], db[3], out);
}

// round 10
// speedup vs baseline: 1.1887x; 1.1320x over previous
#include <cuda_runtime.h>
#include <math.h>

#define BB 2
#define LL 32
#define NSLOPE 0.01f

// ---------------- scratch (static __device__, no allocs) ----------------
__device__ float g_h1p0[2*4*128*128];
__device__ float g_h1p1[2*8*64*64];
__device__ float g_h1p2[2*16*32*32];
__device__ float g_h1p3[2*16*16*16];

__device__ float g_f0[2*4*256*256];
__device__ float g_f1[2*8*128*128];
__device__ float g_f2[2*16*64*64];
__device__ float g_f3[2*16*32*32];

__device__ float g_h2p0[2*4*128*128];
__device__ float g_h2p1[2*8*64*64];
__device__ float g_h2p2[2*16*32*32];
__device__ float g_h2p3[2*16*16*16];

__device__ float g_attn0[64*128*128];
__device__ float g_attn1[64*64*64];
__device__ float g_attn2[64*32*32];
__device__ float g_attn3[64*16*16];

__device__ float g_d0[64*16*32*32];
__device__ float g_d1[64*8*64*64];
__device__ float g_d2[64*4*128*128];

static inline int cdiv(int a, int b) { return (a + b - 1) / b; }

__device__ __forceinline__ float leaky(float v) { return v >= 0.f ? v : NSLOPE * v; }

// Build per-parity 2x2 effective kernel from a 3x3 kernel (upsample-nearest folding).
__device__ __forceinline__ void build_eff(const float* wk, int ey, int ex, float* e) {
    float rs[2][3];
    if (ey == 0) {
        rs[0][0] = wk[0]; rs[0][1] = wk[1]; rs[0][2] = wk[2];
        rs[1][0] = wk[3] + wk[6]; rs[1][1] = wk[4] + wk[7]; rs[1][2] = wk[5] + wk[8];
    } else {
        rs[0][0] = wk[0] + wk[3]; rs[0][1] = wk[1] + wk[4]; rs[0][2] = wk[2] + wk[5];
        rs[1][0] = wk[6]; rs[1][1] = wk[7]; rs[1][2] = wk[8];
    }
#pragma unroll
    for (int a = 0; a < 2; a++) {
        if (ex == 0) { e[a * 2 + 0] = rs[a][0]; e[a * 2 + 1] = rs[a][1] + rs[a][2]; }
        else         { e[a * 2 + 0] = rs[a][0] + rs[a][1]; e[a * 2 + 1] = rs[a][2]; }
    }
}

// ============ encoder: conv5x5+leaky[+feats]+maxpool2, ci-split S, both paths (z) ============
template<int CI, int CO, int COG, int H, int S, int PPB>
__global__ void enc_conv3_t(const float* __restrict__ in2, const float* __restrict__ in1,
                            const float* __restrict__ w, const float* __restrict__ bias,
                            float* __restrict__ f, float* __restrict__ pooled2,
                            float* __restrict__ pooled1) {
    constexpr int HP = H / 2;
    constexpr int NG = CO / COG;
    constexpr int CIG = CI / S;
    static_assert(CI % S == 0, "");
    static_assert((HP * HP) % PPB == 0, "");
    __shared__ float ws[COG * CI * 25];
    __shared__ float red[(S > 1) ? (S - 1) * PPB * COG * 4 : 1];

    int bly = blockIdx.y;
    int cog = bly % NG;
    int n = bly / NG;
    int co0 = cog * COG;
    bool path2 = (blockIdx.z == 0);
    const float* in = path2 ? in2 : in1;
    float* pooled = path2 ? pooled2 : pooled1;

    int tx = threadIdx.x, ty = threadIdx.y;
    int tid = ty * PPB + tx;
    for (int i = tid; i < COG * CI * 25; i += PPB * S)
        ws[i] = w[co0 * CI * 25 + i];
    __syncthreads();

    int p = blockIdx.x * PPB + tx;
    int px = p % HP, py = p / HP;

    float acc[COG][2][2] = {};

    const float* ib = in + (size_t)n * CI * H * H;
#pragma unroll
    for (int i = 0; i < CIG; i++) {
        int ci = ty * CIG + i;
        const float* src = ib + ci * H * H;
        float v[6][6];
#pragma unroll
        for (int r = 0; r < 6; r++) {
            int yy = 2 * py - 2 + r;
            bool oy = (unsigned)yy < (unsigned)H;
#pragma unroll
            for (int c = 0; c < 6; c++) {
                int xx = 2 * px - 2 + c;
                v[r][c] = (oy && (unsigned)xx < (unsigned)H) ? __ldg(src + yy * H + xx) : 0.f;
            }
        }
#pragma unroll
        for (int g = 0; g < COG; g++)
#pragma unroll
            for (int dy = 0; dy < 2; dy++)
#pragma unroll
                for (int dx = 0; dx < 2; dx++)
#pragma unroll
                    for (int ky = 0; ky < 5; ky++)
#pragma unroll
                        for (int kx = 0; kx < 5; kx++)
                            acc[g][dy][dx] += v[dy + ky][dx + kx] * ws[(g * CI + ci) * 25 + ky * 5 + kx];
    }

    if constexpr (S > 1) {
        if (ty > 0) {
            float* r = &red[((ty - 1) * PPB + tx) * (COG * 4)];
#pragma unroll
            for (int g = 0; g < COG; g++)
#pragma unroll
                for (int dy = 0; dy < 2; dy++)
#pragma unroll
                    for (int dx = 0; dx < 2; dx++)
                        r[g * 4 + dy * 2 + dx] = acc[g][dy][dx];
        }
        __syncthreads();
        if (ty > 0) return;
#pragma unroll
        for (int s = 0; s < S - 1; s++) {
            const float* r = &red[(s * PPB + tx) * (COG * 4)];
#pragma unroll
            for (int g = 0; g < COG; g++)
#pragma unroll
                for (int dy = 0; dy < 2; dy++)
#pragma unroll
                    for (int dx = 0; dx < 2; dx++)
                        acc[g][dy][dx] += r[g * 4 + dy * 2 + dx];
        }
    }

#pragma unroll
    for (int g = 0; g < COG; g++) {
        float b = bias[co0 + g];
        float a00 = leaky(acc[g][0][0] + b);
        float a01 = leaky(acc[g][0][1] + b);
        float a10 = leaky(acc[g][1][0] + b);
        float a11 = leaky(acc[g][1][1] + b);
        int coidx = n * CO + co0 + g;
        if (path2) {
            float* fp = f + (size_t)coidx * H * H;
            fp[(2 * py) * H + 2 * px] = a00;
            fp[(2 * py) * H + 2 * px + 1] = a01;
            fp[(2 * py + 1) * H + 2 * px] = a10;
            fp[(2 * py + 1) * H + 2 * px + 1] = a11;
        }
        pooled[((size_t)coidx * HP + py) * HP + px] = fmaxf(fmaxf(a00, a01), fmaxf(a10, a11));
    }
}

// ============ attention, all 4 levels in one kernel ============
template<int C, int HS, int SHIFT>
__device__ __forceinline__ void attn_level(const float* __restrict__ h2p,
                                           const float* __restrict__ h1p,
                                           const int* __restrict__ pts,
                                           float* __restrict__ attn,
                                           int b, int blk, float* qs, float* nqs) {
    constexpr int P = HS * HS;
    int tid = threadIdx.x;
    for (int i = tid; i < LL * C; i += blockDim.x) {
        int l = i / C, c = i % C;
        int qr = pts[(b * LL + l) * 2 + 0] >> SHIFT;
        int qc = pts[(b * LL + l) * 2 + 1] >> SHIFT;
        qs[l * C + c] = h1p[((size_t)(b * C + c)) * P + qr * HS + qc];
    }
    __syncthreads();
    if (tid < LL) {
        float s = 0.f;
#pragma unroll
        for (int c = 0; c < C; c++) s += qs[tid * C + c] * qs[tid * C + c];
        nqs[tid] = fmaxf(sqrtf(s), 1e-8f);
    }
    __syncthreads();

    int p0 = (blk * (int)blockDim.x + tid) * 4;
    if (p0 >= P) return;
    float4 v[C];
    float4 n2 = make_float4(0.f, 0.f, 0.f, 0.f);
#pragma unroll
    for (int c = 0; c < C; c++) {
        v[c] = *(const float4*)(h2p + ((size_t)(b * C + c)) * P + p0);
        n2.x += v[c].x * v[c].x; n2.y += v[c].y * v[c].y;
        n2.z += v[c].z * v[c].z; n2.w += v[c].w * v[c].w;
    }
    float4 inv;
    inv.x = 1.f / fmaxf(sqrtf(n2.x), 1e-8f);
    inv.y = 1.f / fmaxf(sqrtf(n2.y), 1e-8f);
    inv.z = 1.f / fmaxf(sqrtf(n2.z), 1e-8f);
    inv.w = 1.f / fmaxf(sqrtf(n2.w), 1e-8f);
#pragma unroll
    for (int l = 0; l < LL; l++) {
        float4 d = make_float4(0.f, 0.f, 0.f, 0.f);
#pragma unroll
        for (int c = 0; c < C; c++) {
            float q = qs[l * C + c];
            d.x += v[c].x * q; d.y += v[c].y * q;
            d.z += v[c].z * q; d.w += v[c].w * q;
        }
        float rq = 1.f / nqs[l];
        d.x *= inv.x * rq; d.y *= inv.y * rq; d.z *= inv.z * rq; d.w *= inv.w * rq;
        *(float4*)(attn + ((size_t)(b * LL + l)) * P + p0) = d;
    }
}

__global__ void attn_all_k(const float* __restrict__ h2p0, const float* __restrict__ h1p0,
                           const float* __restrict__ h2p1, const float* __restrict__ h1p1,
                           const float* __restrict__ h2p2, const float* __restrict__ h1p2,
                           const float* __restrict__ h2p3, const float* __restrict__ h1p3,
                           const int* __restrict__ pts,
                           float* __restrict__ a0, float* __restrict__ a1,
                           float* __restrict__ a2, float* __restrict__ a3) {
    __shared__ float qs[LL * 16];
    __shared__ float nqs[LL];
    int id = blockIdx.x;
    if (id < 32)      attn_level<4, 128, 1>(h2p0, h1p0, pts, a0, id / 16, id % 16, qs, nqs);
    else if (id < 40) attn_level<8, 64, 2>(h2p1, h1p1, pts, a1, (id - 32) / 4, (id - 32) % 4, qs, nqs);
    else if (id < 42) attn_level<16, 32, 3>(h2p2, h1p2, pts, a2, id - 40, 0, qs, nqs);
    else              attn_level<16, 16, 4>(h2p3, h1p3, pts, a3, id - 42, 0, qs, nqs);
}

// ============ fused decoder: eff-kernel half-res + direct feat, split S (half/feat) ============
// (exact configuration that benched 188.4us)
template<int CH2, int CF, int CO, int COG, int HO, bool LEAKY, bool H2MOD, int S, int PPB>
__global__ void dec_conv3_t(const float* __restrict__ h2, const float* __restrict__ attn,
                            const float* __restrict__ feat, const float* __restrict__ w,
                            const float* __restrict__ bias, float* __restrict__ out) {
    constexpr int CIN = CH2 + 1 + CF;
    constexpr int CHALF = CH2 + 1;
    constexpr int HH = HO / 2;
    constexpr int NG = CO / COG;
    static_assert((HH * HH) % PPB == 0, "");
    __shared__ float ws[COG * CIN * 9];
    __shared__ float weff[COG * CHALF * 16];
    __shared__ float red[(S > 1) ? PPB * COG * 4 : 1];

    int bly = blockIdx.y;
    int cog = bly % NG;
    int n = bly / NG;
    int co0 = cog * COG;
    int tx = threadIdx.x, ty = threadIdx.y;
    int tid = ty * PPB + tx;
    for (int i = tid; i < COG * CIN * 9; i += PPB * S)
        ws[i] = w[co0 * CIN * 9 + i];
    __syncthreads();
    for (int i = tid; i < COG * CHALF * 4; i += PPB * S) {
        int par = i & 3;
        int gc = i >> 2;
        int g = gc / CHALF, ch = gc % CHALF;
        float e[4];
        build_eff(&ws[(g * CIN + ch) * 9], par >> 1, par & 1, e);
        float* o = &weff[gc * 16 + par * 4];
        o[0] = e[0]; o[1] = e[1]; o[2] = e[2]; o[3] = e[3];
    }
    __syncthreads();

    int p = blockIdx.x * PPB + tx;
    int X = p % HH, Y = p / HH;
    int nh2 = H2MOD ? (n % BB) : n;
    int nf = n % BB;

    float acc[COG][2][2] = {};

    // ---- half-res channels (h2 + attn) via per-parity 2x2 effective kernels ----
    if (S == 1 || ty == 0) {
        const float* hb = h2 + (size_t)nh2 * CH2 * HH * HH;
        const float* ab = attn + (size_t)n * HH * HH;
#pragma unroll 4
        for (int ch = 0; ch < CHALF; ch++) {
            const float* src = (ch < CH2) ? (hb + ch * HH * HH) : ab;
            float v[3][3];
#pragma unroll
            for (int r = 0; r < 3; r++) {
                int hy = Y - 1 + r;
                bool oy = (unsigned)hy < (unsigned)HH;
#pragma unroll
                for (int c = 0; c < 3; c++) {
                    int hx = X - 1 + c;
                    v[r][c] = (oy && (unsigned)hx < (unsigned)HH) ? __ldg(src + hy * HH + hx) : 0.f;
                }
            }
#pragma unroll
            for (int g = 0; g < COG; g++) {
                const float* wf = &weff[(g * CHALF + ch) * 16];
#pragma unroll
                for (int dy = 0; dy < 2; dy++)
#pragma unroll
                    for (int dx = 0; dx < 2; dx++)
#pragma unroll
                        for (int a = 0; a < 2; a++)
#pragma unroll
                            for (int b = 0; b < 2; b++)
                                acc[g][dy][dx] += v[((dy + 1) >> 1) + a][((dx + 1) >> 1) + b]
                                                  * wf[(dy * 2 + dx) * 4 + a * 2 + b];
            }
        }
    }

    // ---- full-res feat channels ----
    if (S == 1 || ty == 1) {
        const float* fb = feat + (size_t)nf * CF * HO * HO;
#pragma unroll 4
        for (int cf = 0; cf < CF; cf++) {
            const float* src = fb + cf * HO * HO;
            float v[4][4];
#pragma unroll
            for (int r = 0; r < 4; r++) {
                int yy = 2 * Y - 1 + r;
                bool oy = (unsigned)yy < (unsigned)HO;
#pragma unroll
                for (int c = 0; c < 4; c++) {
                    int xx = 2 * X - 1 + c;
                    v[r][c] = (oy && (unsigned)xx < (unsigned)HO) ? __ldg(src + yy * HO + xx) : 0.f;
                }
            }
#pragma unroll
            for (int g = 0; g < COG; g++)
#pragma unroll
                for (int dy = 0; dy < 2; dy++)
#pragma unroll
                    for (int dx = 0; dx < 2; dx++)
#pragma unroll
                        for (int ky = 0; ky < 3; ky++)
#pragma unroll
                            for (int kx = 0; kx < 3; kx++)
                                acc[g][dy][dx] += v[dy + ky][dx + kx]
                                                  * ws[(g * CIN + CH2 + 1 + cf) * 9 + ky * 3 + kx];
        }
    }

    if constexpr (S > 1) {
        if (ty == 1) {
            float* r = &red[tx * (COG * 4)];
#pragma unroll
            for (int g = 0; g < COG; g++)
#pragma unroll
                for (int dy = 0; dy < 2; dy++)
#pragma unroll
                    for (int dx = 0; dx < 2; dx++)
                        r[g * 4 + dy * 2 + dx] = acc[g][dy][dx];
        }
        __syncthreads();
        if (ty == 1) return;
        const float* r = &red[tx * (COG * 4)];
#pragma unroll
        for (int g = 0; g < COG; g++)
#pragma unroll
            for (int dy = 0; dy < 2; dy++)
#pragma unroll
                for (int dx = 0; dx < 2; dx++)
                    acc[g][dy][dx] += r[g * 4 + dy * 2 + dx];
    }

#pragma unroll
    for (int g = 0; g < COG; g++) {
        float b = bias[co0 + g];
#pragma unroll
        for (int dy = 0; dy < 2; dy++)
#pragma unroll
            for (int dx = 0; dx < 2; dx++) {
                float r = acc[g][dy][dx] + b;
                if (LEAKY) r = leaky(r);
                out[(((size_t)n * CO + co0 + g) * HO + 2 * Y + dy) * HO + 2 * X + dx] = r;
            }
    }
}

// ============ final decoder layer: CO=1, 4x4 output patch, eff-kernel half-res ============
template<int CH2, int CF, int HO, bool LEAKY>
__global__ void dec_conv_p4_t(const float* __restrict__ h2, const float* __restrict__ attn,
                              const float* __restrict__ feat, const float* __restrict__ w,
                              const float* __restrict__ bias, float* __restrict__ out) {
    constexpr int CIN = CH2 + 1 + CF;
    constexpr int CHALF = CH2 + 1;
    constexpr int HH = HO / 2;
    constexpr int QH = HO / 4;
    __shared__ float ws[CIN * 9];
    __shared__ float weff[CHALF * 16];
    int n = blockIdx.y;
    int tid = threadIdx.x;
    for (int i = tid; i < CIN * 9; i += blockDim.x) ws[i] = w[i];
    __syncthreads();
    for (int i = tid; i < CHALF * 4; i += blockDim.x) {
        int par = i & 3, ch = i >> 2;
        float e[4];
        build_eff(&ws[ch * 9], par >> 1, par & 1, e);
        float* o = &weff[ch * 16 + par * 4];
        o[0] = e[0]; o[1] = e[1]; o[2] = e[2]; o[3] = e[3];
    }
    __syncthreads();

    int p = blockIdx.x * blockDim.x + tid;
    int X = p % QH, Y = p / QH;
    int nf = n % BB;

    float acc[4][4] = {};

    // half-res channels: 4x4 halo at rows 2Y-1..2Y+2
    {
        const float* hb = h2 + (size_t)n * CH2 * HH * HH;
        const float* ab = attn + (size_t)n * HH * HH;
#pragma unroll
        for (int ch = 0; ch < CHALF; ch++) {
            const float* src = (ch < CH2) ? (hb + ch * HH * HH) : ab;
            float v[4][4];
#pragma unroll
            for (int r = 0; r < 4; r++) {
                int hy = 2 * Y - 1 + r;
                bool oy = (unsigned)hy < (unsigned)HH;
#pragma unroll
                for (int c = 0; c < 4; c++) {
                    int hx = 2 * X - 1 + c;
                    v[r][c] = (oy && (unsigned)hx < (unsigned)HH) ? __ldg(src + hy * HH + hx) : 0.f;
                }
            }
            const float* wf = &weff[ch * 16];
#pragma unroll
            for (int dy = 0; dy < 4; dy++)
#pragma unroll
                for (int dx = 0; dx < 4; dx++)
#pragma unroll
                    for (int a = 0; a < 2; a++)
#pragma unroll
                        for (int b = 0; b < 2; b++)
                            acc[dy][dx] += v[((dy + 1) >> 1) + a][((dx + 1) >> 1) + b]
                                           * wf[((dy & 1) * 2 + (dx & 1)) * 4 + a * 2 + b];
        }
    }

    // full-res feat channels: 6x6 halo at rows 4Y-1..4Y+4
    {
        const float* fb = feat + (size_t)nf * CF * HO * HO;
#pragma unroll
        for (int cf = 0; cf < CF; cf++) {
            const float* src = fb + cf * HO * HO;
            float v[6][6];
#pragma unroll
            for (int r = 0; r < 6; r++) {
                int yy = 4 * Y - 1 + r;
                bool oy = (unsigned)yy < (unsigned)HO;
#pragma unroll
                for (int c = 0; c < 6; c++) {
                    int xx = 4 * X - 1 + c;
                    v[r][c] = (oy && (unsigned)xx < (unsigned)HO) ? __ldg(src + yy * HO + xx) : 0.f;
                }
            }
            const float* wk = &ws[(CHALF + cf) * 9];
#pragma unroll
            for (int dy = 0; dy < 4; dy++)
#pragma unroll
                for (int dx = 0; dx < 4; dx++)
#pragma unroll
                    for (int ky = 0; ky < 3; ky++)
#pragma unroll
                        for (int kx = 0; kx < 3; kx++)
                            acc[dy][dx] += v[dy + ky][dx + kx] * wk[ky * 3 + kx];
        }
    }

    float b = bias[0];
#pragma unroll
    for (int dy = 0; dy < 4; dy++)
#pragma unroll
        for (int dx = 0; dx < 4; dx++) {
            float r = acc[dy][dx] + b;
            if (LEAKY) r = leaky(r);
            out[((size_t)n * HO + 4 * Y + dy) * HO + 4 * X + dx] = r;
        }
}

// ---------------- launch ----------------
extern "C" void kernel_launch(void* const* d_in, const int* in_sizes, int n_in,
                              void* d_out, int out_size) {
    const float* x1 = (const float*)d_in[0];
    const float* x2 = (const float*)d_in[1];
    const int* pts = (const int*)d_in[2];
    const float* ew[4] = {(const float*)d_in[3], (const float*)d_in[5],
                          (const float*)d_in[7], (const float*)d_in[9]};
    const float* eb[4] = {(const float*)d_in[4], (const float*)d_in[6],
                          (const float*)d_in[8], (const float*)d_in[10]};
    const float* dw[4] = {(const float*)d_in[11], (const float*)d_in[13],
                          (const float*)d_in[15], (const float*)d_in[17]};
    const float* db[4] = {(const float*)d_in[12], (const float*)d_in[14],
                          (const float*)d_in[16], (const float*)d_in[18]};
    float* out = (float*)d_out;

    float *h1p0, *h1p1, *h1p2, *h1p3;
    float *f0, *f1, *f2, *f3;
    float *h2p0, *h2p1, *h2p2, *h2p3;
    float *a0, *a1, *a2, *a3;
    float *dd0, *dd1, *dd2;
    cudaGetSymbolAddress((void**)&h1p0, g_h1p0);
    cudaGetSymbolAddress((void**)&h1p1, g_h1p1);
    cudaGetSymbolAddress((void**)&h1p2, g_h1p2);
    cudaGetSymbolAddress((void**)&h1p3, g_h1p3);
    cudaGetSymbolAddress((void**)&f0, g_f0);
    cudaGetSymbolAddress((void**)&f1, g_f1);
    cudaGetSymbolAddress((void**)&f2, g_f2);
    cudaGetSymbolAddress((void**)&f3, g_f3);
    cudaGetSymbolAddress((void**)&h2p0, g_h2p0);
    cudaGetSymbolAddress((void**)&h2p1, g_h2p1);
    cudaGetSymbolAddress((void**)&h2p2, g_h2p2);
    cudaGetSymbolAddress((void**)&h2p3, g_h2p3);
    cudaGetSymbolAddress((void**)&a0, g_attn0);
    cudaGetSymbolAddress((void**)&a1, g_attn1);
    cudaGetSymbolAddress((void**)&a2, g_attn2);
    cudaGetSymbolAddress((void**)&a3, g_attn3);
    cudaGetSymbolAddress((void**)&dd0, g_d0);
    cudaGetSymbolAddress((void**)&dd1, g_d1);
    cudaGetSymbolAddress((void**)&dd2, g_d2);

    // ---- encoder chain: R9 configuration (measured fastest encoder) ----
    enc_conv3_t<3, 4, 4, 256, 1, 128><<<dim3(128, 2, 2), dim3(128, 1)>>>(x2, x1, ew[0], eb[0], f0, h2p0, h1p0);
    enc_conv3_t<4, 8, 4, 128, 2, 64><<<dim3(64, 4, 2), dim3(64, 2)>>>(h2p0, h1p0, ew[1], eb[1], f1, h2p1, h1p1);
    enc_conv3_t<8, 16, 2, 64, 4, 32><<<dim3(32, 16, 2), dim3(32, 4)>>>(h2p1, h1p1, ew[2], eb[2], f2, h2p2, h1p2);
    enc_conv3_t<16, 16, 2, 32, 8, 32><<<dim3(8, 16, 2), dim3(32, 8)>>>(h2p2, h1p2, ew[3], eb[3], f3, h2p3, h1p3);

    // ---- all attention levels in one kernel ----
    attn_all_k<<<44, 256>>>(h2p0, h1p0, h2p1, h1p1, h2p2, h1p2, h2p3, h1p3,
                            pts, a0, a1, a2, a3);

    // ---- decoder: R5 configuration (measured fastest decoder, benched 188.4) ----
    dec_conv3_t<16, 16, 16, 8, 32, true, true, 2, 64><<<dim3(4, 128), dim3(64, 2)>>>(h2p3, a3, f3, dw[0], db[0], dd0);
    dec_conv3_t<16, 16, 8, 8, 64, true, false, 2, 64><<<dim3(16, 64), dim3(64, 2)>>>(dd0, a2, f2, dw[1], db[1], dd1);
    dec_conv3_t<8, 8, 4, 4, 128, true, false, 2, 64><<<dim3(64, 64), dim3(64, 2)>>>(dd1, a1, f1, dw[2], db[2], dd2);
    dec_conv_p4_t<4, 4, 256, false><<<dim3(32, 64), 128>>>(dd2, a0, f0, dw[3], db[3], out);
}